// round 17
// baseline (speedup 1.0000x reference)
#include <cuda_runtime.h>
#include <cuda_fp16.h>
#include <cstdint>
#include <math.h>

#define S_LEN 2048
#define HID   2048
#define NHQ   16
#define NKV   4
#define HD    128
#define WIN   1024

// ---------------- scratch (no cudaMalloc allowed) ----------------
__device__ __half   g_hsh[S_LEN * HID];
__device__ uint32_t g_qh[S_LEN * (NHQ * HD) / 2];
__device__ uint32_t g_kh[S_LEN * (NKV * HD) / 2];
__device__ uint32_t g_vh[S_LEN * (NKV * HD) / 2];
__device__ uint32_t g_attnh[S_LEN * (NHQ * HD) / 2];
// fp16 row-major weights: [K][N/2] u32
__device__ uint32_t g_wqp[HID * (NHQ * HD) / 2];
__device__ uint32_t g_wkp[HID * (NKV * HD) / 2];
__device__ uint32_t g_wvp[HID * (NKV * HD) / 2];
__device__ uint32_t g_wop[(NHQ * HD) * HID / 2];

__device__ __forceinline__ uint32_t pack2(float a, float b) {
    __half2 h = __floats2half2_rn(a, b);
    return *reinterpret_cast<uint32_t*>(&h);
}
__device__ __forceinline__ void mma_h16(float c[4], const uint32_t a[4], const uint32_t b[2]) {
    asm volatile("mma.sync.aligned.m16n8k16.row.col.f32.f16.f16.f32 "
        "{%0,%1,%2,%3}, {%4,%5,%6,%7}, {%8,%9}, {%0,%1,%2,%3};"
        : "+f"(c[0]), "+f"(c[1]), "+f"(c[2]), "+f"(c[3])
        : "r"(a[0]), "r"(a[1]), "r"(a[2]), "r"(a[3]), "r"(b[0]), "r"(b[1]));
}
__device__ __forceinline__ void ldsm_x4(uint32_t r[4], uint32_t addr) {
    asm volatile("ldmatrix.sync.aligned.m8n8.x4.shared.b16 {%0,%1,%2,%3}, [%4];"
        : "=r"(r[0]), "=r"(r[1]), "=r"(r[2]), "=r"(r[3]) : "r"(addr));
}
__device__ __forceinline__ void ldsm_x4_t(uint32_t r[4], uint32_t addr) {
    asm volatile("ldmatrix.sync.aligned.m8n8.x4.trans.shared.b16 {%0,%1,%2,%3}, [%4];"
        : "=r"(r[0]), "=r"(r[1]), "=r"(r[2]), "=r"(r[3]) : "r"(addr));
}
__device__ __forceinline__ uint32_t smem_u32(const void* p) {
    uint32_t a;
    asm("{ .reg .u64 t; cvta.to.shared.u64 t, %1; cvt.u32.u64 %0, t; }" : "=r"(a) : "l"(p));
    return a;
}
__device__ __forceinline__ void cp16(uint32_t s, const void* g) {
    asm volatile("cp.async.ca.shared.global [%0], [%1], 16;" :: "r"(s), "l"(g));
}
#define CP_COMMIT() asm volatile("cp.async.commit_group;" ::: "memory")
#define CP_WAIT1()  asm volatile("cp.async.wait_group 1;" ::: "memory")
#define CP_WAIT0()  asm volatile("cp.async.wait_group 0;" ::: "memory")

// ---------------------------------------------------------------------------
// one-launch prep: hs fp32->fp16 + all weights to fp16 row-major [K][N/2] u32.
// ---------------------------------------------------------------------------
#define CONV_U (S_LEN * HID / 8)
#define SEG_Q (HID * (NHQ * HD) / 8)
#define SEG_K (HID * (NKV * HD) / 8)
#define SEG_O ((NHQ * HD) * HID / 8)
#define PREP_U (CONV_U + SEG_Q + 2 * SEG_K + SEG_O)

__global__ void prep_all(const float* __restrict__ hs,
                         const float* __restrict__ Wq, const float* __restrict__ Wk,
                         const float* __restrict__ Wv, const float* __restrict__ Wo) {
    int u = blockIdx.x * blockDim.x + threadIdx.x;
    if (u < CONV_U) {
        int i = u * 8;
        float4 v0 = *reinterpret_cast<const float4*>(hs + i);
        float4 v1 = *reinterpret_cast<const float4*>(hs + i + 4);
        uint4 o = { pack2(v0.x, v0.y), pack2(v0.z, v0.w), pack2(v1.x, v1.y), pack2(v1.z, v1.w) };
        *reinterpret_cast<uint4*>(g_hsh + i) = o;
        return;
    }
    u -= CONV_U;
    const float* W; uint32_t* Wp;
    if (u < SEG_Q)                  { W = Wq; Wp = g_wqp; }
    else if (u < SEG_Q + SEG_K)     { W = Wk; Wp = g_wkp; u -= SEG_Q; }
    else if (u < SEG_Q + 2 * SEG_K) { W = Wv; Wp = g_wvp; u -= SEG_Q + SEG_K; }
    else                            { W = Wo; Wp = g_wop; u -= SEG_Q + 2 * SEG_K; }
    int i = u * 8;
    float4 a = *reinterpret_cast<const float4*>(W + i);
    float4 b = *reinterpret_cast<const float4*>(W + i + 4);
    uint4 o = { pack2(a.x, a.y), pack2(a.z, a.w), pack2(b.x, b.y), pack2(b.z, b.w) };
    *reinterpret_cast<uint4*>(Wp + u * 4) = o;
}

// ---------------------------------------------------------------------------
// fp16 cp.async GEMM, CTA (MI*32) x 128, K-tile 64, 3 stages, 2 CTAs/SM.
// 8 warps (2 x 4), warp tile (MI*16) x 64. A frags ldmatrix, B ldmatrix.trans.
// One barrier per K-tile. EPI==0: fp32 out. EPI==1: fused QKV + RoPE.
// ---------------------------------------------------------------------------
#define AS2 36
#define TNG 128
#define BS2 (TNG / 2 + 4)          // 68 u32 per k-row
#define B_U32 (64 * BS2)           // 4352

template<int MI, int EPI>
__global__ __launch_bounds__(256, 2) void gemm_h(const __half* __restrict__ Ah, int K,
                                                 const uint32_t* __restrict__ Wp0, int nb0,
                                                 const uint32_t* __restrict__ Wp1, int nb1,
                                                 const uint32_t* __restrict__ Wp2,
                                                 float* __restrict__ Cout, int NOUT,
                                                 const float* __restrict__ fc,
                                                 const int* __restrict__ pos) {
    constexpr int A_U32 = MI * 32 * AS2;
    constexpr int STG = A_U32 + B_U32;

    extern __shared__ uint32_t smg[];
    const uint32_t sbase = smem_u32(smg);

    const int tid  = threadIdx.x;
    const int lane = tid & 31;
    const int wid  = tid >> 5;
    const int wm   = wid & 1;
    const int wn   = wid >> 1;
    const int g    = lane >> 2;
    const int tig  = lane & 3;
    const int brow = blockIdx.y * (MI * 32);

    const int arow  = (lane & 7) + ((lane & 8) ? 8 : 0);
    const int acsel = (lane & 16) ? 4 : 0;
    const int vcsel = (lane & 16) ? 1 : 0;

    const uint32_t* Wp; int N, cloc, dest = 0;
    {
        int bx = blockIdx.x;
        if (bx < nb0)            { Wp = Wp0; N = (EPI ? NHQ * HD : NOUT); cloc = bx * TNG; dest = 0; }
        else if (bx < nb0 + nb1) { Wp = Wp1; N = NKV * HD; cloc = (bx - nb0) * TNG; dest = 1; }
        else                     { Wp = Wp2; N = NKV * HD; cloc = (bx - nb0 - nb1) * TNG; dest = 2; }
    }
    const int N2 = N >> 1;
    const int c2loc = cloc >> 1;

    float acc[MI][4][4];
#pragma unroll
    for (int mi = 0; mi < MI; ++mi)
#pragma unroll
        for (int ni = 0; ni < 4; ++ni)
#pragma unroll
            for (int f = 0; f < 4; ++f) acc[mi][ni][f] = 0.f;

    const int iters = K / 64;

#define ISSUE_STAGE(st, k0)                                                          \
    do {                                                                             \
        uint32_t soff = sbase + (uint32_t)((st) * STG) * 4u;                         \
        _Pragma("unroll")                                                            \
        for (int i = 0; i < MI; ++i) {                                               \
            int idx = tid + i * 256;                                                 \
            int r = idx >> 3, ch = idx & 7;                                          \
            cp16(soff + (uint32_t)(r * AS2 * 4 + ch * 16),                           \
                 &Ah[(size_t)(brow + r) * K + (k0) + ch * 8]);                       \
        }                                                                            \
        _Pragma("unroll")                                                            \
        for (int i = 0; i < 4; ++i) {                                                \
            int idx = tid + i * 256;                                                 \
            int r = idx >> 4, ch = idx & 15;                                         \
            cp16(soff + (uint32_t)(A_U32 * 4 + r * BS2 * 4 + ch * 16),               \
                 &Wp[(size_t)((k0) + r) * N2 + c2loc + ch * 4]);                     \
        }                                                                            \
        CP_COMMIT();                                                                 \
    } while (0)

    ISSUE_STAGE(0, 0);
    ISSUE_STAGE(1, 64);

    for (int kt = 0; kt < iters; ++kt) {
        CP_WAIT1();
        __syncthreads();

        const uint32_t stg_base = sbase + (uint32_t)((kt % 3) * STG) * 4u;
        const uint32_t bbase = stg_base + (uint32_t)A_U32 * 4u;

#pragma unroll
        for (int kk = 0; kk < 4; ++kk) {
            const int kb2 = kk * 8;
            uint32_t af[MI][4], bf[2][4];
#pragma unroll
            for (int mi = 0; mi < MI; ++mi) {
                int r0 = wm * (MI * 16) + mi * 16 + arow;
                ldsm_x4(af[mi], stg_base + (uint32_t)(r0 * AS2 + kb2 + acsel) * 4u);
            }
#pragma unroll
            for (int p = 0; p < 2; ++p)
                ldsm_x4_t(bf[p], bbase + (uint32_t)((kk * 16 + arow) * BS2
                                        + wn * 16 + (2 * p + vcsel) * 4) * 4u);
#pragma unroll
            for (int mi = 0; mi < MI; ++mi) {
                mma_h16(acc[mi][0], af[mi], bf[0]);
                mma_h16(acc[mi][1], af[mi], bf[0] + 2);
                mma_h16(acc[mi][2], af[mi], bf[1]);
                mma_h16(acc[mi][3], af[mi], bf[1] + 2);
            }
        }

        if (kt + 2 < iters) {
            ISSUE_STAGE((kt + 2) % 3, (kt + 2) * 64);
        } else {
            CP_COMMIT();
        }
    }
#undef ISSUE_STAGE

    if (EPI == 0) {
#pragma unroll
        for (int mi = 0; mi < MI; ++mi) {
            int r0 = brow + wm * (MI * 16) + mi * 16 + g;
#pragma unroll
            for (int ni = 0; ni < 4; ++ni) {
                int c0 = cloc + wn * 32 + ni * 8 + 2 * tig;
                float2 v0 = make_float2(acc[mi][ni][0], acc[mi][ni][1]);
                float2 v1 = make_float2(acc[mi][ni][2], acc[mi][ni][3]);
                *reinterpret_cast<float2*>(&Cout[(size_t)r0 * N + c0])       = v0;
                *reinterpret_cast<float2*>(&Cout[(size_t)(r0 + 8) * N + c0]) = v1;
            }
        }
    } else {
        uint32_t* dst = (dest == 0) ? g_qh : (dest == 1) ? g_kh : g_vh;
        const int rstr = (dest == 0) ? (NHQ * HD / 2) : (NKV * HD / 2);
#pragma unroll
        for (int mi = 0; mi < MI; ++mi) {
            int r0 = brow + wm * (MI * 16) + mi * 16 + g;
            int r1 = r0 + 8;
            int p0 = pos[r0], p1 = pos[r1];
#pragma unroll
            for (int ni = 0; ni < 4; ++ni) {
                int c0 = cloc + wn * 32 + ni * 8 + 2 * tig;
                float a0 = acc[mi][ni][0], b0 = acc[mi][ni][1];
                float a1 = acc[mi][ni][2], b1 = acc[mi][ni][3];
                if (dest < 2) {
                    int dcol = c0 & (HD - 1);
                    float2 cs0 = *reinterpret_cast<const float2*>(&fc[(size_t)p0 * HD + dcol]);
                    float2 cs1 = *reinterpret_cast<const float2*>(&fc[(size_t)p1 * HD + dcol]);
                    float na0 = a0 * cs0.x - b0 * cs0.y;
                    float nb0 = a0 * cs0.y + b0 * cs0.x;
                    float na1 = a1 * cs1.x - b1 * cs1.y;
                    float nb1 = a1 * cs1.y + b1 * cs1.x;
                    a0 = na0; b0 = nb0; a1 = na1; b1 = nb1;
                }
                dst[(size_t)r0 * rstr + (c0 >> 1)] = pack2(a0, b0);
                dst[(size_t)r1 * rstr + (c0 >> 1)] = pack2(a1, b1);
            }
        }
    }
}

// ---------------------------------------------------------------------------
// Flash attention (unchanged R16 winner): 64 q-rows/CTA, 4 warps, 3 CTAs/SM,
// single-buffered K/V, exp2 softmax, boundary-only masking, register P.
// ---------------------------------------------------------------------------
#define QS2 68
#define KVS 68
#define K_OFF (64 * QS2)
#define V_OFF (K_OFF + 64 * KVS)
#define ATT_SMEM ((V_OFF + 64 * KVS) * 4)

__global__ __launch_bounds__(128, 3) void attn_h(uint32_t* __restrict__ outh) {
    extern __shared__ uint32_t smu[];
    const uint32_t sbase = smem_u32(smu);

    const int q0  = blockIdx.x * 64;
    const int h   = blockIdx.y;
    const int kvh = h >> 2;
    const int tid = threadIdx.x;
    const int lane = tid & 31;
    const int wq  = tid >> 5;
    const int g   = lane >> 2;
    const int tig = lane & 3;
    const int rb  = wq * 16;

    const int arow  = (lane & 7) + ((lane & 8) ? 8 : 0);
    const int acsel = (lane & 16) ? 4 : 0;
    const int krow  = (lane & 7) + ((lane & 16) ? 8 : 0);
    const int kcsel = (lane & 8) ? 4 : 0;
    const int vcsel = (lane & 16) ? 1 : 0;

    const float NEG = -1e30f;
    const __half2 qscale = __float2half2_rn(0.08838834764831845f * 1.4426950408889634f);

#pragma unroll
    for (int i = 0; i < 8; ++i) {
        int idx = i * 128 + tid;
        int r = idx >> 4, j4 = (idx & 15) * 4;
        uint4 v = *reinterpret_cast<const uint4*>(&g_qh[(size_t)(q0 + r) * (NHQ * HD / 2) + h * (HD / 2) + j4]);
        __half2* hv = reinterpret_cast<__half2*>(&v);
        hv[0] = __hmul2(hv[0], qscale);
        hv[1] = __hmul2(hv[1], qscale);
        hv[2] = __hmul2(hv[2], qscale);
        hv[3] = __hmul2(hv[3], qscale);
        *reinterpret_cast<uint4*>(&smu[r * QS2 + j4]) = v;
    }

    float m0 = NEG, m1 = NEG, l0 = 0.f, l1 = 0.f;
    float o[16][4];
#pragma unroll
    for (int nf = 0; nf < 16; ++nf)
#pragma unroll
        for (int f = 0; f < 4; ++f) o[nf][f] = 0.f;

    int lo = q0 - (WIN - 1); if (lo < 0) lo = 0;
    const int kb_lo = lo >> 6;
    const int kb_hi = q0 >> 6;

    const uint32_t qfrag = sbase + (uint32_t)((rb + arow) * QS2 + acsel) * 4u;
    const uint32_t kbuf = sbase + (uint32_t)K_OFF * 4u;
    const uint32_t vbuf = sbase + (uint32_t)V_OFF * 4u;

    for (int kb = kb_lo; kb <= kb_hi; ++kb) {
        const int t0 = kb * 64;
#pragma unroll
        for (int i = 0; i < 8; ++i) {
            int idx = tid + i * 128;
            int r = idx >> 4, c = (idx & 15) * 4;
            cp16(kbuf + (uint32_t)(r * KVS + c) * 4u,
                 &g_kh[(size_t)(t0 + r) * (NKV * HD / 2) + kvh * (HD / 2) + c]);
        }
#pragma unroll
        for (int i = 0; i < 8; ++i) {
            int idx = tid + i * 128;
            int r = idx >> 4, c = (idx & 15) * 4;
            cp16(vbuf + (uint32_t)(r * KVS + c) * 4u,
                 &g_vh[(size_t)(t0 + r) * (NKV * HD / 2) + kvh * (HD / 2) + c]);
        }
        CP_COMMIT();
        CP_WAIT0();
        __syncthreads();

        float s[8][4];
#pragma unroll
        for (int nf = 0; nf < 8; ++nf)
#pragma unroll
            for (int f = 0; f < 4; ++f) s[nf][f] = 0.f;

#pragma unroll
        for (int ks = 0; ks < 8; ++ks) {
            uint32_t a[4];
            ldsm_x4(a, qfrag + (uint32_t)(ks * 8) * 4u);
#pragma unroll
            for (int nf = 0; nf < 8; nf += 2) {
                uint32_t b[4];
                ldsm_x4(b, kbuf + (uint32_t)((nf * 8 + krow) * KVS + ks * 8 + kcsel) * 4u);
                mma_h16(s[nf],     a, b);
                mma_h16(s[nf + 1], a, b + 2);
            }
        }

        if (kb == kb_hi || t0 < lo) {
            const int r0g = q0 + rb + g, r1g = r0g + 8;
#pragma unroll
            for (int nf = 0; nf < 8; ++nf) {
                int c0 = t0 + nf * 8 + 2 * tig;
                int c1 = c0 + 1;
                bool ok00 = (c0 <= r0g) && (r0g - c0 < WIN);
                bool ok01 = (c1 <= r0g) && (r0g - c1 < WIN);
                bool ok10 = (c0 <= r1g) && (r1g - c0 < WIN);
                bool ok11 = (c1 <= r1g) && (r1g - c1 < WIN);
                s[nf][0] = ok00 ? s[nf][0] : NEG;
                s[nf][1] = ok01 ? s[nf][1] : NEG;
                s[nf][2] = ok10 ? s[nf][2] : NEG;
                s[nf][3] = ok11 ? s[nf][3] : NEG;
            }
        }

        float mt0 = NEG, mt1 = NEG;
#pragma unroll
        for (int nf = 0; nf < 8; ++nf) {
            mt0 = fmaxf(mt0, fmaxf(s[nf][0], s[nf][1]));
            mt1 = fmaxf(mt1, fmaxf(s[nf][2], s[nf][3]));
        }
        mt0 = fmaxf(mt0, __shfl_xor_sync(0xffffffffu, mt0, 1));
        mt0 = fmaxf(mt0, __shfl_xor_sync(0xffffffffu, mt0, 2));
        mt1 = fmaxf(mt1, __shfl_xor_sync(0xffffffffu, mt1, 1));
        mt1 = fmaxf(mt1, __shfl_xor_sync(0xffffffffu, mt1, 2));

        float mn0 = fmaxf(m0, mt0), mn1 = fmaxf(m1, mt1);
        float esc0 = exp2f(m0 - mn0);
        float esc1 = exp2f(m1 - mn1);

        uint32_t pa[4][4];
        float rs0 = 0.f, rs1 = 0.f;
#pragma unroll
        for (int nf = 0; nf < 8; ++nf) {
            float p00 = exp2f(s[nf][0] - mn0);
            float p01 = exp2f(s[nf][1] - mn0);
            float p10 = exp2f(s[nf][2] - mn1);
            float p11 = exp2f(s[nf][3] - mn1);
            rs0 += p00 + p01;
            rs1 += p10 + p11;
            const int kc = nf >> 1;
            if ((nf & 1) == 0) {
                pa[kc][0] = pack2(p00, p01);
                pa[kc][1] = pack2(p10, p11);
            } else {
                pa[kc][2] = pack2(p00, p01);
                pa[kc][3] = pack2(p10, p11);
            }
        }
        rs0 += __shfl_xor_sync(0xffffffffu, rs0, 1);
        rs0 += __shfl_xor_sync(0xffffffffu, rs0, 2);
        rs1 += __shfl_xor_sync(0xffffffffu, rs1, 1);
        rs1 += __shfl_xor_sync(0xffffffffu, rs1, 2);

        l0 = l0 * esc0 + rs0; m0 = mn0;
        l1 = l1 * esc1 + rs1; m1 = mn1;

#pragma unroll
        for (int nf = 0; nf < 16; ++nf) {
            o[nf][0] *= esc0; o[nf][1] *= esc0;
            o[nf][2] *= esc1; o[nf][3] *= esc1;
        }

#pragma unroll
        for (int kc = 0; kc < 4; ++kc) {
#pragma unroll
            for (int nf = 0; nf < 16; nf += 2) {
                uint32_t b[4];
                ldsm_x4_t(b, vbuf + (uint32_t)((kc * 16 + arow) * KVS + (nf + vcsel) * 4) * 4u);
                mma_h16(o[nf],     pa[kc], b);
                mma_h16(o[nf + 1], pa[kc], b + 2);
            }
        }
        __syncthreads();
    }

    const float inv0 = 1.f / l0, inv1 = 1.f / l1;
    const int qr0 = q0 + rb + g, qr1 = qr0 + 8;
#pragma unroll
    for (int nf = 0; nf < 16; ++nf) {
        int c2 = h * (HD / 2) + nf * 4 + tig;
        outh[(size_t)qr0 * (NHQ * HD / 2) + c2] = pack2(o[nf][0] * inv0, o[nf][1] * inv0);
        outh[(size_t)qr1 * (NHQ * HD / 2) + c2] = pack2(o[nf][2] * inv1, o[nf][3] * inv1);
    }
}

// ---------------------------------------------------------------------------
extern "C" void kernel_launch(void* const* d_in, const int* in_sizes, int n_in,
                              void* d_out, int out_size) {
    const float* hs  = (const float*)d_in[0];
    const float* fc  = (const float*)d_in[1];
    const int*   pos = (const int*)d_in[4];
    const float* Wq  = (const float*)d_in[5];
    const float* Wk  = (const float*)d_in[6];
    const float* Wv  = (const float*)d_in[7];
    const float* Wo  = (const float*)d_in[8];
    float* out = (float*)d_out;

    __half *hsh;
    uint32_t *attnh, *wqp, *wkp, *wvp, *wop;
    cudaGetSymbolAddress((void**)&hsh,   g_hsh);
    cudaGetSymbolAddress((void**)&attnh, g_attnh);
    cudaGetSymbolAddress((void**)&wqp,   g_wqp);
    cudaGetSymbolAddress((void**)&wkp,   g_wkp);
    cudaGetSymbolAddress((void**)&wvp,   g_wvp);
    cudaGetSymbolAddress((void**)&wop,   g_wop);

    prep_all<<<PREP_U / 256, 256>>>(hs, Wq, Wk, Wv, Wo);

    constexpr int SMEM_QKV = 3 * (2 * 32 * AS2 + B_U32) * 4;   // MI=2: 79872 B
    constexpr int SMEM_O   = 3 * (4 * 32 * AS2 + B_U32) * 4;   // MI=4: 107520 B
    cudaFuncSetAttribute((const void*)gemm_h<2, 1>, cudaFuncAttributeMaxDynamicSharedMemorySize, SMEM_QKV);
    cudaFuncSetAttribute((const void*)gemm_h<4, 0>, cudaFuncAttributeMaxDynamicSharedMemorySize, SMEM_O);
    cudaFuncSetAttribute((const void*)attn_h,       cudaFuncAttributeMaxDynamicSharedMemorySize, ATT_SMEM);

    // fused QKV + RoPE: 64x128 tiles, 24 col blocks x 32 row blocks = 768 CTAs
    gemm_h<2, 1><<<dim3(24, 32), 256, SMEM_QKV>>>(hsh, HID, wqp, 16, wkp, 4, wvp,
                                                  nullptr, 0, fc, pos);

    // attention: 64 q-rows per CTA, 4 warps, 3 CTAs/SM, register-resident P
    attn_h<<<dim3(S_LEN / 64, NHQ), 128, ATT_SMEM>>>(attnh);

    // O projection: 128x128 tiles, 16x16 = 256 CTAs (single wave)
    gemm_h<4, 0><<<dim3(16, 16), 256, SMEM_O>>>((const __half*)attnh, NHQ * HD, wop, 16,
                                                nullptr, 0, nullptr, out, HID, nullptr, nullptr);
}